// round 1
// baseline (speedup 1.0000x reference)
#include <cuda_runtime.h>
#include <math_constants.h>

#define Nn 64
#define Ll 1024
#define Hh 1024

typedef unsigned long long u64;

// Scratch (device globals; no allocation in kernel_launch).
__device__ float g_dh[Nn * Hh];     // decoder_hidden @ W_h^T   [N, H]
__device__ float g_score[Nn * Ll];  // pre-softmax scores       [N, L]

// tanh via EX2+RCP (MUFU pipe; overlaps with FMA GEMM issue).
// Exact at saturation: x>>0 -> e=inf -> 1; x<<0 -> e=0 -> -1.
__device__ __forceinline__ float tanh_fast(float x) {
    float e = __expf(2.0f * x);
    return 1.0f - __fdividef(2.0f, e + 1.0f);
}

__device__ __forceinline__ u64 pack2(float lo, float hi) {
    u64 r;
    asm("mov.b64 %0, {%1, %2};" : "=l"(r) : "f"(lo), "f"(hi));
    return r;
}
__device__ __forceinline__ void unpack2(float& lo, float& hi, u64 v) {
    asm("mov.b64 {%0, %1}, %2;" : "=f"(lo), "=f"(hi) : "l"(v));
}
// Packed dual-FMA: 2 fp32 FMAs per instruction (sm_100+ f32x2 pipe).
__device__ __forceinline__ void fma2(u64& acc, u64 a, u64 b) {
    asm("fma.rn.f32x2 %0, %1, %2, %0;" : "+l"(acc) : "l"(a), "l"(b));
}

// ---------------------------------------------------------------------------
// dh[n,k] = sum_h dec[n,h] * Wh[k,h]   — one warp per output element.
// ---------------------------------------------------------------------------
__global__ __launch_bounds__(256) void dh_kernel(const float* __restrict__ dec,
                                                 const float* __restrict__ Wh) {
    int w    = (blockIdx.x * blockDim.x + threadIdx.x) >> 5;  // 0..65535
    int lane = threadIdx.x & 31;
    int n = w >> 10;
    int k = w & 1023;
    const float4* dp = (const float4*)(dec + (size_t)n * Hh);
    const float4* wp = (const float4*)(Wh + (size_t)k * Hh);
    float acc = 0.f;
#pragma unroll
    for (int it = 0; it < 8; ++it) {
        float4 a = dp[it * 32 + lane];
        float4 b = wp[it * 32 + lane];
        acc += a.x * b.x + a.y * b.y + a.z * b.z + a.w * b.w;
    }
#pragma unroll
    for (int o = 16; o; o >>= 1) acc += __shfl_xor_sync(0xffffffffu, acc, o);
    if (lane == 0) g_dh[w] = acc;
}

// ---------------------------------------------------------------------------
// Fused: eh-tile GEMM (E @ Ws^T) + tanh(eh+dh)*v reduction -> score[n,l].
// Block = 128 rows (nl) x full K=1024 (looped in 16 chunks of 64).
// Each score element written exactly once => deterministic, no atomics.
// ---------------------------------------------------------------------------
#define BM 128
#define BN 64
#define BK 16

__global__ __launch_bounds__(256) void score_kernel(const float* __restrict__ E,
                                                    const float* __restrict__ Ws,
                                                    const float* __restrict__ v) {
    __shared__ float As[BK][BM + 4];   // [h-chunk][row], padded
    __shared__ float Bs[BK][BN + 4];   // [h-chunk][k-col], padded
    __shared__ float sred[BM][17];

    const int tid = threadIdx.x;
    const int tx = tid & 15;           // k-col group
    const int ty = tid >> 4;           // row group (rows ty*8 .. ty*8+7)
    const int row0 = blockIdx.x * BM;  // global nl row base
    const int n = row0 >> 10;          // whole block lies in one n (128 | 1024)

    float score8[8];
#pragma unroll
    for (int i = 0; i < 8; ++i) score8[i] = 0.f;

    for (int kc = 0; kc < Hh / BN; ++kc) {
        u64 accp[4][4];  // packed fp32 pairs: rows (2*i2, 2*i2+1) x 4 k-cols
#pragma unroll
        for (int i2 = 0; i2 < 4; ++i2)
#pragma unroll
            for (int j = 0; j < 4; ++j) accp[i2][j] = 0ull;

        const int kbase = kc * BN;

        for (int hb = 0; hb < Hh; hb += BK) {
            // Load A tile (128 x 16), 2 float4 per thread, store transposed.
#pragma unroll
            for (int t = 0; t < 2; ++t) {
                int f4 = tid + t * 256;
                int r  = f4 >> 2;
                int hq = (f4 & 3) << 2;
                float4 a = *(const float4*)(E + (size_t)(row0 + r) * Hh + hb + hq);
                As[hq + 0][r] = a.x; As[hq + 1][r] = a.y;
                As[hq + 2][r] = a.z; As[hq + 3][r] = a.w;
            }
            // Load B tile (64 x 16), 1 float4 per thread, store transposed.
            {
                int k  = tid >> 2;
                int hq = (tid & 3) << 2;
                float4 b = *(const float4*)(Ws + (size_t)(kbase + k) * Hh + hb + hq);
                Bs[hq + 0][k] = b.x; Bs[hq + 1][k] = b.y;
                Bs[hq + 2][k] = b.z; Bs[hq + 3][k] = b.w;
            }
            __syncthreads();
#pragma unroll
            for (int kk = 0; kk < BK; ++kk) {
                u64 a2[4];
                float bv[4];
#pragma unroll
                for (int i2 = 0; i2 < 4; ++i2)
                    a2[i2] = *(const u64*)&As[kk][ty * 8 + 2 * i2];
#pragma unroll
                for (int j = 0; j < 4; ++j) bv[j] = Bs[kk][tx + 16 * j];
#pragma unroll
                for (int j = 0; j < 4; ++j) {
                    u64 b2 = pack2(bv[j], bv[j]);
#pragma unroll
                    for (int i2 = 0; i2 < 4; ++i2) fma2(accp[i2][j], a2[i2], b2);
                }
            }
            __syncthreads();
        }

        // Epilogue for this k-chunk: score += tanh(eh + dh) * v
#pragma unroll
        for (int j = 0; j < 4; ++j) {
            const int c = kbase + tx + 16 * j;
            const float dhv = g_dh[(n << 10) + c];
            const float vv  = __ldg(v + c);
#pragma unroll
            for (int i2 = 0; i2 < 4; ++i2) {
                float lo, hi;
                unpack2(lo, hi, accp[i2][j]);
                score8[2 * i2 + 0] += tanh_fast(lo + dhv) * vv;
                score8[2 * i2 + 1] += tanh_fast(hi + dhv) * vv;
            }
        }
    }

    // Cross-thread (tx) reduction of per-thread k-partials, fixed order.
#pragma unroll
    for (int i = 0; i < 8; ++i) sred[ty * 8 + i][tx] = score8[i];
    __syncthreads();
    if (tid < BM) {
        float s = 0.f;
#pragma unroll
        for (int t = 0; t < 16; ++t) s += sred[tid][t];
        g_score[row0 + tid] = s;
    }
}

// ---------------------------------------------------------------------------
// Masked softmax over L per row n. mask!=0 => PAD => weight 0.
// ---------------------------------------------------------------------------
__global__ __launch_bounds__(256) void softmax_kernel(const int* __restrict__ mask,
                                                      float* __restrict__ attn) {
    __shared__ float red[256];
    const int n = blockIdx.x;
    const int tid = threadIdx.x;

    float s[4];
    int msk[4];
    float lmax = -CUDART_INF_F;
#pragma unroll
    for (int q = 0; q < 4; ++q) {
        int l = tid + 256 * q;
        msk[q] = mask[n * Ll + l];
        s[q] = g_score[n * Ll + l];
        if (!msk[q]) lmax = fmaxf(lmax, s[q]);
    }
    red[tid] = lmax;
    __syncthreads();
    for (int o = 128; o; o >>= 1) {
        if (tid < o) red[tid] = fmaxf(red[tid], red[tid + o]);
        __syncthreads();
    }
    const float mx = red[0];
    __syncthreads();

    float p[4];
    float lsum = 0.f;
#pragma unroll
    for (int q = 0; q < 4; ++q) {
        p[q] = msk[q] ? 0.f : __expf(s[q] - mx);
        lsum += p[q];
    }
    red[tid] = lsum;
    __syncthreads();
    for (int o = 128; o; o >>= 1) {
        if (tid < o) red[tid] += red[tid + o];
        __syncthreads();
    }
    const float inv = 1.0f / red[0];
#pragma unroll
    for (int q = 0; q < 4; ++q) attn[n * Ll + tid + 256 * q] = p[q] * inv;
}

// ---------------------------------------------------------------------------
// context[n,h] = sum_l attn[n,l] * E[n,l,h].  grid (n, 2 halves of H).
// ---------------------------------------------------------------------------
__global__ __launch_bounds__(128) void context_kernel(const float* __restrict__ E,
                                                      const float* __restrict__ attn,
                                                      float* __restrict__ ctx) {
    __shared__ float sa[Ll];
    const int n = blockIdx.x;
    const int tid = threadIdx.x;
#pragma unroll
    for (int q = 0; q < 8; ++q) sa[tid + 128 * q] = attn[n * Ll + tid + 128 * q];
    __syncthreads();

    const int h4 = blockIdx.y * 128 + tid;  // float4 index within row (0..255)
    const float4* Ep = (const float4*)(E + (size_t)n * Ll * Hh);
    float4 acc = make_float4(0.f, 0.f, 0.f, 0.f);
#pragma unroll 4
    for (int l = 0; l < Ll; ++l) {
        float a = sa[l];
        float4 e = Ep[(size_t)l * 256 + h4];
        acc.x += a * e.x; acc.y += a * e.y;
        acc.z += a * e.z; acc.w += a * e.w;
    }
    ((float4*)ctx)[n * 256 + h4] = acc;
}

// ---------------------------------------------------------------------------
extern "C" void kernel_launch(void* const* d_in, const int* in_sizes, int n_in,
                              void* d_out, int out_size) {
    const float* dec  = (const float*)d_in[0];  // [N, H]
    const float* E    = (const float*)d_in[1];  // [N, L, H]
    const int*   mask = (const int*)  d_in[2];  // [N, L] (bool -> int32)
    const float* Wh   = (const float*)d_in[3];  // [H, H]
    const float* Ws   = (const float*)d_in[4];  // [H, H]
    const float* v    = (const float*)d_in[5];  // [H]

    float* out  = (float*)d_out;
    float* ctx  = out;             // [N, H]  = 65536 floats
    float* attn = out + Nn * Hh;   // [N, L]  = 65536 floats

    dh_kernel<<<(Nn * Hh * 32) / 256, 256>>>(dec, Wh);
    score_kernel<<<(Nn * Ll) / BM, 256>>>(E, Ws, v);
    softmax_kernel<<<Nn, 256>>>(mask, attn);
    context_kernel<<<dim3(Nn, 2), 128>>>(E, attn, ctx);
}

// round 3
// speedup vs baseline: 3.3659x; 3.3659x over previous
#include <cuda_runtime.h>
#include <cuda_bf16.h>
#include <math_constants.h>
#include <cstdint>

#define Nn 64
#define Ll 1024
#define Hh 1024

// ---------------------------------------------------------------------------
// Device scratch
// ---------------------------------------------------------------------------
__device__ float g_dh[Nn * Hh];                         // dec @ Wh^T
__device__ float g_scoreP[4][Nn * Ll];                  // per-col-block score partials
__device__ __align__(16) __nv_bfloat16 g_Bhi[Hh * Hh];  // Ws split hi
__device__ __align__(16) __nv_bfloat16 g_Blo[Hh * Hh];  // Ws split lo
__device__ float4 g_ctxP[4][Nn * (Hh / 4)];             // context partials

// ---------------------------------------------------------------------------
// Helpers
// ---------------------------------------------------------------------------
__device__ __forceinline__ uint32_t smem_u32(const void* p) {
    uint32_t a;
    asm("{ .reg .u64 t; cvta.to.shared.u64 t, %1; cvt.u32.u64 %0, t; }" : "=r"(a) : "l"(p));
    return a;
}
__device__ __forceinline__ float tanh_fast(float x) {
    float e = __expf(2.0f * x);
    return 1.0f - __fdividef(2.0f, e + 1.0f);
}
__device__ __forceinline__ unsigned pk2(__nv_bfloat16 a, __nv_bfloat16 b) {
    return (unsigned)__bfloat16_as_ushort(a) | ((unsigned)__bfloat16_as_ushort(b) << 16);
}
__device__ __forceinline__ void ldsm_x4(uint32_t* r, uint32_t addr) {
    asm volatile("ldmatrix.sync.aligned.m8n8.x4.shared.b16 {%0,%1,%2,%3}, [%4];"
                 : "=r"(r[0]), "=r"(r[1]), "=r"(r[2]), "=r"(r[3]) : "r"(addr));
}
__device__ __forceinline__ void mma_bf16(float* c, const uint32_t* a, uint32_t b0, uint32_t b1) {
    asm volatile("mma.sync.aligned.m16n8k16.row.col.f32.bf16.bf16.f32 "
                 "{%0,%1,%2,%3}, {%4,%5,%6,%7}, {%8,%9}, {%0,%1,%2,%3};"
                 : "+f"(c[0]), "+f"(c[1]), "+f"(c[2]), "+f"(c[3])
                 : "r"(a[0]), "r"(a[1]), "r"(a[2]), "r"(a[3]), "r"(b0), "r"(b1));
}
__device__ __forceinline__ void cp_async16(uint32_t dst, const void* src) {
    asm volatile("cp.async.cg.shared.global [%0], [%1], 16;" :: "r"(dst), "l"(src) : "memory");
}
#define CP_COMMIT() asm volatile("cp.async.commit_group;" ::: "memory")
#define CP_WAIT0()  asm volatile("cp.async.wait_group 0;" ::: "memory")

// ---------------------------------------------------------------------------
// Split Ws -> bf16 hi/lo (once, 4 MB)
// ---------------------------------------------------------------------------
__global__ __launch_bounds__(256) void bsplit_kernel(const float* __restrict__ Ws) {
    int i = blockIdx.x * 256 + threadIdx.x;  // float4 index
    float4 w = ((const float4*)Ws)[i];
    float vv[4] = {w.x, w.y, w.z, w.w};
    __nv_bfloat16 h[4], l[4];
#pragma unroll
    for (int j = 0; j < 4; ++j) {
        h[j] = __float2bfloat16_rn(vv[j]);
        l[j] = __float2bfloat16_rn(vv[j] - __bfloat162float(h[j]));
    }
    ((uint2*)g_Bhi)[i] = make_uint2(pk2(h[0], h[1]), pk2(h[2], h[3]));
    ((uint2*)g_Blo)[i] = make_uint2(pk2(l[0], l[1]), pk2(l[2], l[3]));
}

// ---------------------------------------------------------------------------
// dh[n,k] = sum_h dec[n,h]*Wh[k,h] — verified round-1 version (warp/output).
// ---------------------------------------------------------------------------
__global__ __launch_bounds__(256) void dh_kernel(const float* __restrict__ dec,
                                                 const float* __restrict__ Wh) {
    int w = (blockIdx.x * blockDim.x + threadIdx.x) >> 5;
    int lane = threadIdx.x & 31;
    int n = w >> 10;
    int k = w & 1023;
    const float4* dp = (const float4*)(dec + (size_t)n * Hh);
    const float4* wp = (const float4*)(Wh + (size_t)k * Hh);
    float acc = 0.f;
#pragma unroll
    for (int it = 0; it < 8; ++it) {
        float4 a = dp[it * 32 + lane];
        float4 b = wp[it * 32 + lane];
        acc += a.x * b.x + a.y * b.y + a.z * b.z + a.w * b.w;
    }
#pragma unroll
    for (int o = 16; o; o >>= 1) acc += __shfl_xor_sync(0xffffffffu, acc, o);
    if (lane == 0) g_dh[w] = acc;
}

// ---------------------------------------------------------------------------
// Fused score kernel: bf16x3 mma.sync GEMM (E @ Ws^T) + tanh(.)·v epilogue.
// Grid (512 row-blocks, 4 col-blocks). CTA 128x256, 512 threads, K=1024.
// ---------------------------------------------------------------------------
#define PITCH 40           // bf16 per smem row (32 data + 8 pad) -> 80 bytes
#define PITCHB 80
#define A_BYTES (128 * PITCHB)   // 10240
#define B_BYTES (256 * PITCHB)   // 20480
#define STAGE_BYTES (2 * A_BYTES + 2 * B_BYTES)  // 61440
#define SM_DH   0
#define SM_V    1024
#define SM_SRED 2048            // 128*4 floats
#define SM_STG  4096
#define SM_TOTAL (SM_STG + 2 * STAGE_BYTES)  // 126976

__global__ __launch_bounds__(512, 1) void score_kernel(const float* __restrict__ E,
                                                       const float* __restrict__ v) {
    extern __shared__ char smem[];
    const uint32_t sb = smem_u32(smem);
    const int tid = threadIdx.x;
    const int lane = tid & 31;
    const int wid = tid >> 5;
    const int wm = wid & 3;    // m group: rows wm*32..+31
    const int wn = wid >> 2;   // n group: cols wn*64..+63
    const int row0 = blockIdx.x * 128;
    const int n = row0 >> 10;
    const int jbase = blockIdx.y * 256;

    // dh/v slices for this col-block
    if (tid < 256) {
        ((float*)(smem + SM_DH))[tid] = g_dh[(n << 10) + jbase + tid];
        ((float*)(smem + SM_V))[tid] = v[jbase + tid];
    }

    const float* Erow = E + (size_t)row0 * Hh;

    // per-thread loader indices
    const int a_r0 = tid >> 3, a_q0 = tid & 7;          // A f4 #tid
    const int a_r1 = (tid + 512) >> 3, a_q1 = (tid + 512) & 7;
    const int b_r = tid >> 2, b_q = tid & 3;            // B 16B #tid (first 1024)
    const int b_r2 = (tid + 512) >> 2, b_q2 = (tid + 512) & 3;

    float acc[2][8][4];
#pragma unroll
    for (int mt = 0; mt < 2; ++mt)
#pragma unroll
        for (int nt = 0; nt < 8; ++nt)
#pragma unroll
            for (int e = 0; e < 4; ++e) acc[mt][nt][e] = 0.f;

    // ldmatrix source addresses (per thread), relative to buffer bases
    const int a_row = (lane & 15);
    const int a_koff = (lane >> 4) << 3;
    const uint32_t a_off = (uint32_t)(a_row * PITCHB + a_koff * 2);
    const int b_row = ((lane >> 4) << 3) + (lane & 7);
    const int b_koff = ((lane >> 3) & 1) << 3;
    const uint32_t b_off = (uint32_t)(b_row * PITCHB + b_koff * 2);

    // --- stage loader pieces ---
    auto load_A_regs = [&](int kb, float4& f0, float4& f1) {
        f0 = *(const float4*)(Erow + (size_t)a_r0 * Hh + kb + a_q0 * 4);
        f1 = *(const float4*)(Erow + (size_t)a_r1 * Hh + kb + a_q1 * 4);
    };
    auto sts_A = [&](uint32_t stg, const float4& f0, const float4& f1) {
        const float va[2][4] = {{f0.x, f0.y, f0.z, f0.w}, {f1.x, f1.y, f1.z, f1.w}};
        const int rr[2] = {a_r0, a_r1};
        const int qq[2] = {a_q0, a_q1};
#pragma unroll
        for (int t = 0; t < 2; ++t) {
            __nv_bfloat16 h[4], l[4];
#pragma unroll
            for (int j = 0; j < 4; ++j) {
                h[j] = __float2bfloat16_rn(va[t][j]);
                l[j] = __float2bfloat16_rn(va[t][j] - __bfloat162float(h[j]));
            }
            uint32_t o = (uint32_t)(rr[t] * PITCHB + qq[t] * 8);
            *(uint2*)(smem + SM_STG + stg + o) = make_uint2(pk2(h[0], h[1]), pk2(h[2], h[3]));
            *(uint2*)(smem + SM_STG + stg + A_BYTES + o) =
                make_uint2(pk2(l[0], l[1]), pk2(l[2], l[3]));
        }
    };
    auto cp_B = [&](uint32_t stg, int kb) {
        uint32_t bh = sb + SM_STG + stg + 2 * A_BYTES;
        uint32_t bl = bh + B_BYTES;
        uint32_t o1 = (uint32_t)(b_r * PITCHB + b_q * 16);
        uint32_t o2 = (uint32_t)(b_r2 * PITCHB + b_q2 * 16);
        const __nv_bfloat16* sh1 = g_Bhi + (size_t)(jbase + b_r) * Hh + kb + b_q * 8;
        const __nv_bfloat16* sh2 = g_Bhi + (size_t)(jbase + b_r2) * Hh + kb + b_q2 * 8;
        const __nv_bfloat16* sl1 = g_Blo + (size_t)(jbase + b_r) * Hh + kb + b_q * 8;
        const __nv_bfloat16* sl2 = g_Blo + (size_t)(jbase + b_r2) * Hh + kb + b_q2 * 8;
        cp_async16(bh + o1, sh1);
        cp_async16(bh + o2, sh2);
        cp_async16(bl + o1, sl1);
        cp_async16(bl + o2, sl2);
    };

    // --- prologue: stage 0, chunk 0 ---
    {
        float4 f0, f1;
        load_A_regs(0, f0, f1);
        cp_B(0, 0);
        CP_COMMIT();
        sts_A(0, f0, f1);
        CP_WAIT0();
    }
    __syncthreads();

    for (int c = 0; c < 32; ++c) {
        const uint32_t stg = (uint32_t)((c & 1) * STAGE_BYTES);
        const uint32_t stgn = (uint32_t)(((c + 1) & 1) * STAGE_BYTES);

        float4 nf0, nf1;
        if (c + 1 < 32) {
            load_A_regs((c + 1) * 32, nf0, nf1);
            cp_B(stgn, (c + 1) * 32);
            CP_COMMIT();
        }

        // --- compute chunk c ---
        const uint32_t sAh = sb + SM_STG + stg;
        const uint32_t sAl = sAh + A_BYTES;
        const uint32_t sBh = sAl + A_BYTES;
        const uint32_t sBl = sBh + B_BYTES;
#pragma unroll
        for (int ks = 0; ks < 2; ++ks) {
            const uint32_t ko = (uint32_t)(ks * 32);  // 16 bf16 = 32 bytes
            uint32_t ah[2][4], al[2][4];
#pragma unroll
            for (int mt = 0; mt < 2; ++mt) {
                uint32_t ao = (uint32_t)((wm * 32 + mt * 16) * PITCHB) + a_off + ko;
                ldsm_x4(ah[mt], sAh + ao);
                ldsm_x4(al[mt], sAl + ao);
            }
#pragma unroll
            for (int np = 0; np < 4; ++np) {
                uint32_t bo = (uint32_t)((wn * 64 + np * 16) * PITCHB) + b_off + ko;
                uint32_t bh[4], bl[4];
                ldsm_x4(bh, sBh + bo);
                ldsm_x4(bl, sBl + bo);
#pragma unroll
                for (int mt = 0; mt < 2; ++mt) {
                    mma_bf16(acc[mt][np * 2 + 0], ah[mt], bh[0], bh[1]);
                    mma_bf16(acc[mt][np * 2 + 1], ah[mt], bh[2], bh[3]);
                    mma_bf16(acc[mt][np * 2 + 0], al[mt], bh[0], bh[1]);
                    mma_bf16(acc[mt][np * 2 + 1], al[mt], bh[2], bh[3]);
                    mma_bf16(acc[mt][np * 2 + 0], ah[mt], bl[0], bl[1]);
                    mma_bf16(acc[mt][np * 2 + 1], ah[mt], bl[2], bl[3]);
                }
            }
        }

        if (c + 1 < 32) {
            sts_A(stgn, nf0, nf1);
            CP_WAIT0();
        }
        __syncthreads();
    }

    // --- epilogue: score partial = sum_j tanh(eh + dh)*v ---
    const float* dhs = (const float*)(smem + SM_DH);
    const float* vs = (const float*)(smem + SM_V);
    float part[4] = {0.f, 0.f, 0.f, 0.f};
#pragma unroll
    for (int mt = 0; mt < 2; ++mt)
#pragma unroll
        for (int nt = 0; nt < 8; ++nt)
#pragma unroll
            for (int e = 0; e < 4; ++e) {
                int col = wn * 64 + nt * 8 + (lane & 3) * 2 + (e & 1);
                float val = tanh_fast(acc[mt][nt][e] + dhs[col]) * vs[col];
                part[mt * 2 + (e >> 1)] += val;
            }
#pragma unroll
    for (int p = 0; p < 4; ++p) {
        part[p] += __shfl_xor_sync(0xffffffffu, part[p], 1);
        part[p] += __shfl_xor_sync(0xffffffffu, part[p], 2);
    }
    float* sred = (float*)(smem + SM_SRED);
    if ((lane & 3) == 0) {
#pragma unroll
        for (int mt = 0; mt < 2; ++mt)
#pragma unroll
            for (int rr = 0; rr < 2; ++rr) {
                int row = wm * 32 + mt * 16 + (lane >> 2) + rr * 8;
                sred[row * 4 + wn] = part[mt * 2 + rr];
            }
    }
    __syncthreads();
    if (tid < 128) {
        g_scoreP[blockIdx.y][row0 + tid] =
            sred[tid * 4] + sred[tid * 4 + 1] + sred[tid * 4 + 2] + sred[tid * 4 + 3];
    }
}

// ---------------------------------------------------------------------------
// Masked softmax (sums 4 col-block partials)
// ---------------------------------------------------------------------------
__global__ __launch_bounds__(256) void softmax_kernel(const int* __restrict__ mask,
                                                      float* __restrict__ attn) {
    __shared__ float red[256];
    const int n = blockIdx.x;
    const int tid = threadIdx.x;

    float s[4];
    int msk[4];
    float lmax = -CUDART_INF_F;
#pragma unroll
    for (int q = 0; q < 4; ++q) {
        int l = tid + 256 * q;
        msk[q] = mask[n * Ll + l];
        s[q] = g_scoreP[0][n * Ll + l] + g_scoreP[1][n * Ll + l] +
               g_scoreP[2][n * Ll + l] + g_scoreP[3][n * Ll + l];
        if (!msk[q]) lmax = fmaxf(lmax, s[q]);
    }
    red[tid] = lmax;
    __syncthreads();
    for (int o = 128; o; o >>= 1) {
        if (tid < o) red[tid] = fmaxf(red[tid], red[tid + o]);
        __syncthreads();
    }
    const float mx = red[0];
    __syncthreads();

    float p[4];
    float lsum = 0.f;
#pragma unroll
    for (int q = 0; q < 4; ++q) {
        p[q] = msk[q] ? 0.f : __expf(s[q] - mx);
        lsum += p[q];
    }
    red[tid] = lsum;
    __syncthreads();
    for (int o = 128; o; o >>= 1) {
        if (tid < o) red[tid] += red[tid + o];
        __syncthreads();
    }
    const float inv = 1.0f / red[0];
#pragma unroll
    for (int q = 0; q < 4; ++q) attn[n * Ll + tid + 256 * q] = p[q] * inv;
}

// ---------------------------------------------------------------------------
// Context: 4 L-chunk partials, then reduce.
// ---------------------------------------------------------------------------
__global__ __launch_bounds__(128) void context_kernel(const float* __restrict__ E,
                                                      const float* __restrict__ attn) {
    __shared__ float sa[256];
    __shared__ float4 red[128];
    const int n = blockIdx.x, hc = blockIdx.y, lc = blockIdx.z;
    const int tid = threadIdx.x;
    sa[tid] = attn[n * Ll + lc * 256 + tid];
    sa[tid + 128] = attn[n * Ll + lc * 256 + tid + 128];
    __syncthreads();

    const int c = tid & 31;
    const int lg = tid >> 5;
    const float4* Ep = (const float4*)(E + (size_t)n * Ll * Hh) +
                       (size_t)(lc * 256) * 256 + hc * 32 + c;
    float4 acc = make_float4(0.f, 0.f, 0.f, 0.f);
    const int l0 = lg * 64;
#pragma unroll 4
    for (int l = 0; l < 64; ++l) {
        float a = sa[l0 + l];
        float4 e = Ep[(size_t)(l0 + l) * 256];
        acc.x += a * e.x; acc.y += a * e.y;
        acc.z += a * e.z; acc.w += a * e.w;
    }
    red[tid] = acc;
    __syncthreads();
    if (tid < 32) {
        float4 s = red[tid];
#pragma unroll
        for (int g = 1; g < 4; ++g) {
            float4 o = red[tid + 32 * g];
            s.x += o.x; s.y += o.y; s.z += o.z; s.w += o.w;
        }
        g_ctxP[lc][n * 256 + hc * 32 + tid] = s;
    }
}

__global__ __launch_bounds__(256) void ctx_reduce_kernel(float4* __restrict__ ctx4) {
    int i = blockIdx.x * 256 + threadIdx.x;
    float4 a = g_ctxP[0][i], b = g_ctxP[1][i], c = g_ctxP[2][i], d = g_ctxP[3][i];
    ctx4[i] = make_float4(a.x + b.x + c.x + d.x, a.y + b.y + c.y + d.y,
                          a.z + b.z + c.z + d.z, a.w + b.w + c.w + d.w);
}

// ---------------------------------------------------------------------------
extern "C" void kernel_launch(void* const* d_in, const int* in_sizes, int n_in,
                              void* d_out, int out_size) {
    const float* dec  = (const float*)d_in[0];
    const float* E    = (const float*)d_in[1];
    const int*   mask = (const int*)  d_in[2];
    const float* Wh   = (const float*)d_in[3];
    const float* Ws   = (const float*)d_in[4];
    const float* v    = (const float*)d_in[5];

    float* out  = (float*)d_out;
    float* ctx  = out;
    float* attn = out + Nn * Hh;

    cudaFuncSetAttribute(score_kernel, cudaFuncAttributeMaxDynamicSharedMemorySize, SM_TOTAL);

    bsplit_kernel<<<(Hh * Hh / 4) / 256, 256>>>(Ws);
    dh_kernel<<<(Nn * Hh * 32) / 256, 256>>>(dec, Wh);
    score_kernel<<<dim3((Nn * Ll) / 128, 4), 512, SM_TOTAL>>>(E, v);
    softmax_kernel<<<Nn, 256>>>(mask, attn);
    context_kernel<<<dim3(Nn, Hh / 128, 4), 128>>>(E, attn);
    ctx_reduce_kernel<<<(Nn * Hh / 4) / 256, 256>>>((float4*)ctx);
}